// round 2
// baseline (speedup 1.0000x reference)
#include <cuda_runtime.h>
#include <cuda_bf16.h>
#include <limits.h>

#define N_NODES 50000
#define N_EDGES 800000
#define IN_DIM  256
#define HID     128
#define LEAKY   0.01f

// ---------------- scratch (static device globals; no allocation) -------------
// NOTE: these are ONLY referenced from device code. Passing a __device__
// global as a kernel argument from host code yields the host shadow address
// (that was the round-1 bug).
__device__ float g_z[N_NODES * HID];      // current layer z = fc(h)
__device__ float g_h1[N_NODES * HID];     // layer-1 output (post ELU)
__device__ float g_ssrc[N_NODES];         // z[n] . a[:D]
__device__ float g_sdst[N_NODES];         // z[n] . a[D:]
__device__ float g_e[N_EDGES];            // leaky-relu'd logits
__device__ float g_ex[N_EDGES];           // exp(e - m[dst])
__device__ int   g_mmax[N_NODES];         // float-as-ordered-int max
__device__ float g_denom[N_NODES];
__device__ int   g_cnt[N_NODES];
__device__ int   g_off[N_NODES + 1];
__device__ int   g_cur[N_NODES];
__device__ int   g_eid[N_EDGES];          // CSR (by dst) -> edge id

// ---------------- CSR build --------------------------------------------------
__global__ void zero_cnt_kernel() {
    int i = blockIdx.x * blockDim.x + threadIdx.x;
    if (i < N_NODES) g_cnt[i] = 0;
}

__global__ void hist_kernel(const int* __restrict__ dst) {
    int i = blockIdx.x * blockDim.x + threadIdx.x;
    if (i < N_EDGES) atomicAdd(&g_cnt[dst[i]], 1);
}

__global__ void scan_kernel() {
    __shared__ int sums[1024];
    int tid = threadIdx.x;
    const int chunk = (N_NODES + 1023) / 1024;
    int begin = tid * chunk;
    int end   = begin + chunk; if (end > N_NODES) end = N_NODES;
    if (begin > N_NODES) begin = N_NODES;
    int s = 0;
    for (int i = begin; i < end; ++i) s += g_cnt[i];
    sums[tid] = s;
    __syncthreads();
    for (int off = 1; off < 1024; off <<= 1) {
        int add = 0;
        if (tid >= off) add = sums[tid - off];
        __syncthreads();
        sums[tid] += add;
        __syncthreads();
    }
    int prefix = (tid == 0) ? 0 : sums[tid - 1];
    for (int i = begin; i < end; ++i) {
        g_off[i] = prefix;
        g_cur[i] = prefix;
        prefix += g_cnt[i];
    }
    if (tid == 0) g_off[N_NODES] = sums[1023];
}

__global__ void fill_kernel(const int* __restrict__ dst) {
    int i = blockIdx.x * blockDim.x + threadIdx.x;
    if (i < N_EDGES) {
        int pos = atomicAdd(&g_cur[dst[i]], 1);
        g_eid[pos] = i;
    }
}

// ---------------- per-layer reset -------------------------------------------
__global__ void reset_nodes_kernel() {
    int i = blockIdx.x * blockDim.x + threadIdx.x;
    if (i < N_NODES) {
        g_mmax[i]  = INT_MIN;
        g_denom[i] = 0.f;
    }
}

// ---------------- GEMM: g_z[N,128] = A[N,K] @ W[128,K]^T + b ----------------
// BM=64, BN=128, BK=32, 256 threads, 8x4 register tile per thread.
// UseExt=true  -> A = Aext (external input h)
// UseExt=false -> A = g_h1 (internal layer-1 output)
template <int K, bool UseExt>
__global__ __launch_bounds__(256) void gemm_kernel(
    const float* __restrict__ Aext, const float* __restrict__ W,
    const float* __restrict__ bias)
{
    const float* __restrict__ A = UseExt ? Aext : (const float*)g_h1;

    __shared__ __align__(16) float hs[32][65];    // [k][row], padded
    __shared__ __align__(16) float ws[32][132];   // [k][col]
    int tid  = threadIdx.x;
    int trow = tid >> 5;       // 0..7  -> 8 rows each
    int tcol = tid & 31;       // 0..31 -> 4 cols each
    int m0   = blockIdx.x * 64;

    float acc[8][4];
#pragma unroll
    for (int i = 0; i < 8; ++i)
#pragma unroll
        for (int j = 0; j < 4; ++j) acc[i][j] = 0.f;

    for (int k0 = 0; k0 < K; k0 += 32) {
#pragma unroll
        for (int t = tid; t < 64 * 32; t += 256) {
            int r = t >> 5, kk = t & 31;
            int gr = m0 + r;
            hs[kk][r] = (gr < N_NODES) ? A[gr * K + k0 + kk] : 0.f;
        }
#pragma unroll
        for (int t = tid; t < 128 * 32; t += 256) {
            int c = t >> 5, kk = t & 31;
            ws[kk][c] = W[c * K + k0 + kk];
        }
        __syncthreads();
#pragma unroll
        for (int kk = 0; kk < 32; ++kk) {
            float4 wv = *(const float4*)&ws[kk][tcol * 4];
            float av[8];
#pragma unroll
            for (int i = 0; i < 8; ++i) av[i] = hs[kk][trow * 8 + i];
#pragma unroll
            for (int i = 0; i < 8; ++i) {
                acc[i][0] += av[i] * wv.x;
                acc[i][1] += av[i] * wv.y;
                acc[i][2] += av[i] * wv.z;
                acc[i][3] += av[i] * wv.w;
            }
        }
        __syncthreads();
    }
    float4 bv = *(const float4*)&bias[tcol * 4];
#pragma unroll
    for (int i = 0; i < 8; ++i) {
        int gr = m0 + trow * 8 + i;
        if (gr < N_NODES) {
            float4 o;
            o.x = acc[i][0] + bv.x; o.y = acc[i][1] + bv.y;
            o.z = acc[i][2] + bv.z; o.w = acc[i][3] + bv.w;
            *(float4*)&g_z[gr * 128 + tcol * 4] = o;
        }
    }
}

// ---------------- per-node attention scalars: s_src, s_dst ------------------
__global__ void attn_kernel(const float* __restrict__ a) {
    int gt   = blockIdx.x * blockDim.x + threadIdx.x;
    int node = gt >> 5;
    int lane = gt & 31;
    if (node >= N_NODES) return;
    float4 zv = ((const float4*)g_z)[node * 32 + lane];
    float4 as = ((const float4*)a)[lane];
    float4 ad = ((const float4*)a)[lane + 32];
    float ss = zv.x * as.x + zv.y * as.y + zv.z * as.z + zv.w * as.w;
    float sd = zv.x * ad.x + zv.y * ad.y + zv.z * ad.z + zv.w * ad.w;
#pragma unroll
    for (int o = 16; o > 0; o >>= 1) {
        ss += __shfl_down_sync(0xffffffffu, ss, o);
        sd += __shfl_down_sync(0xffffffffu, sd, o);
    }
    if (lane == 0) { g_ssrc[node] = ss; g_sdst[node] = sd; }
}

// ---------------- edge logits + segment max ---------------------------------
__global__ void edge_e_kernel(const int* __restrict__ src,
                              const int* __restrict__ dst,
                              const float* __restrict__ ab_ptr) {
    int i = blockIdx.x * blockDim.x + threadIdx.x;
    if (i >= N_EDGES) return;
    float e = g_ssrc[src[i]] + g_sdst[dst[i]] + ab_ptr[0];
    e = (e > 0.f) ? e : LEAKY * e;
    g_e[i] = e;
    int xf  = __float_as_int(e);
    int key = (xf >= 0) ? xf : (xf ^ 0x7fffffff);
    atomicMax(&g_mmax[dst[i]], key);
}

// ---------------- exp + segment sum -----------------------------------------
__global__ void edge_exp_kernel(const int* __restrict__ dst) {
    int i = blockIdx.x * blockDim.x + threadIdx.x;
    if (i >= N_EDGES) return;
    int d   = dst[i];
    int key = g_mmax[d];
    float m = __int_as_float((key >= 0) ? key : (key ^ 0x7fffffff));
    float ex = __expf(g_e[i] - m);
    g_ex[i] = ex;
    atomicAdd(&g_denom[d], ex);
}

// ---------------- atomic-free weighted aggregation + ELU --------------------
// ToExt=true -> write external out pointer; false -> write g_h1
template <bool ToExt>
__global__ void aggregate_kernel(const int* __restrict__ src,
                                 float* __restrict__ out_ext) {
    float* __restrict__ out = ToExt ? out_ext : (float*)g_h1;
    int gt   = blockIdx.x * blockDim.x + threadIdx.x;
    int node = gt >> 5;
    int lane = gt & 31;
    if (node >= N_NODES) return;
    int beg = g_off[node];
    int end = g_off[node + 1];
    float inv = (end > beg) ? (1.f / g_denom[node]) : 0.f;
    float4 acc = make_float4(0.f, 0.f, 0.f, 0.f);
    for (int s = beg; s < end; ++s) {
        int   eid = g_eid[s];                 // uniform within the warp
        float wgt = g_ex[eid] * inv;
        int   sn  = src[eid];
        float4 zv = ((const float4*)g_z)[sn * 32 + lane];
        acc.x += wgt * zv.x; acc.y += wgt * zv.y;
        acc.z += wgt * zv.z; acc.w += wgt * zv.w;
    }
    // ELU (alpha = 1)
    acc.x = (acc.x > 0.f) ? acc.x : (__expf(acc.x) - 1.f);
    acc.y = (acc.y > 0.f) ? acc.y : (__expf(acc.y) - 1.f);
    acc.z = (acc.z > 0.f) ? acc.z : (__expf(acc.z) - 1.f);
    acc.w = (acc.w > 0.f) ? acc.w : (__expf(acc.w) - 1.f);
    ((float4*)out)[node * 32 + lane] = acc;
}

// ---------------- launch ------------------------------------------------------
extern "C" void kernel_launch(void* const* d_in, const int* in_sizes, int n_in,
                              void* d_out, int out_size) {
    const float* h    = (const float*)d_in[0];
    const int*   src  = (const int*)d_in[1];
    const int*   dst  = (const int*)d_in[2];
    const float* W1   = (const float*)d_in[3];
    const float* b1   = (const float*)d_in[4];
    const float* a1   = (const float*)d_in[5];
    const float* ab1  = (const float*)d_in[6];
    const float* W2   = (const float*)d_in[7];
    const float* b2   = (const float*)d_in[8];
    const float* a2   = (const float*)d_in[9];
    const float* ab2  = (const float*)d_in[10];
    float* out = (float*)d_out;

    const int NB_N  = (N_NODES + 255) / 256;       // node-parallel
    const int NB_E  = (N_EDGES + 255) / 256;       // edge-parallel
    const int NB_W  = (N_NODES + 7) / 8;           // warp-per-node
    const int NB_G  = (N_NODES + 63) / 64;         // gemm row tiles

    // CSR by dst (topology only; shared by both layers)
    zero_cnt_kernel<<<NB_N, 256>>>();
    hist_kernel<<<NB_E, 256>>>(dst);
    scan_kernel<<<1, 1024>>>();
    fill_kernel<<<NB_E, 256>>>(dst);

    // ----- layer 1 -----
    reset_nodes_kernel<<<NB_N, 256>>>();
    gemm_kernel<IN_DIM, true><<<NB_G, 256>>>(h, W1, b1);
    attn_kernel<<<NB_W, 256>>>(a1);
    edge_e_kernel<<<NB_E, 256>>>(src, dst, ab1);
    edge_exp_kernel<<<NB_E, 256>>>(dst);
    aggregate_kernel<false><<<NB_W, 256>>>(src, nullptr);

    // ----- layer 2 -----
    reset_nodes_kernel<<<NB_N, 256>>>();
    gemm_kernel<HID, false><<<NB_G, 256>>>(nullptr, W2, b2);
    attn_kernel<<<NB_W, 256>>>(a2);
    edge_e_kernel<<<NB_E, 256>>>(src, dst, ab2);
    edge_exp_kernel<<<NB_E, 256>>>(dst);
    aggregate_kernel<true><<<NB_W, 256>>>(src, out);
}

// round 4
// speedup vs baseline: 1.2719x; 1.2719x over previous
#include <cuda_runtime.h>
#include <cuda_bf16.h>
#include <cstdint>
#include <limits.h>

#define N_NODES 50000
#define N_EDGES 800000
#define IN_DIM  256
#define HID     128
#define LEAKY   0.01f
#define NEG_INF __int_as_float(0xff800000)

// ---------------- scratch (device globals; device-side use ONLY) -------------
__device__ __align__(16) float g_z[N_NODES * HID];   // z = fc(h) (pre-activation)
__device__ __align__(16) float g_h1[N_NODES * HID];  // layer-1 output (post ELU)
__device__ float g_ssrc[N_NODES];
__device__ float g_sdst[N_NODES];
__device__ int   g_cnt[N_NODES];
__device__ int   g_off[N_NODES + 1];
__device__ int   g_cur[N_NODES];
__device__ int   g_eid[N_EDGES];

// ---------------- CSR build --------------------------------------------------
__global__ void zero_cnt_kernel() {
    int i = blockIdx.x * blockDim.x + threadIdx.x;
    if (i < N_NODES) g_cnt[i] = 0;
}
__global__ void hist_kernel(const int* __restrict__ dst) {
    int i = blockIdx.x * blockDim.x + threadIdx.x;
    if (i < N_EDGES) atomicAdd(&g_cnt[dst[i]], 1);
}
__global__ void scan_kernel() {
    __shared__ int sums[1024];
    int tid = threadIdx.x;
    const int chunk = (N_NODES + 1023) / 1024;
    int begin = tid * chunk;
    int end   = begin + chunk; if (end > N_NODES) end = N_NODES;
    if (begin > N_NODES) begin = N_NODES;
    int s = 0;
    for (int i = begin; i < end; ++i) s += g_cnt[i];
    sums[tid] = s;
    __syncthreads();
    for (int off = 1; off < 1024; off <<= 1) {
        int add = 0;
        if (tid >= off) add = sums[tid - off];
        __syncthreads();
        sums[tid] += add;
        __syncthreads();
    }
    int prefix = (tid == 0) ? 0 : sums[tid - 1];
    for (int i = begin; i < end; ++i) {
        g_off[i] = prefix;
        g_cur[i] = prefix;
        prefix += g_cnt[i];
    }
    if (tid == 0) g_off[N_NODES] = sums[1023];
}
__global__ void fill_kernel(const int* __restrict__ dst) {
    int i = blockIdx.x * blockDim.x + threadIdx.x;
    if (i < N_EDGES) {
        int pos = atomicAdd(&g_cur[dst[i]], 1);
        g_eid[pos] = i;
    }
}

// ---------------- tf32 helpers ----------------------------------------------
__device__ __forceinline__ uint32_t tf32r(float x) {
    uint32_t u;
    asm("cvt.rn.tf32.f32 %0, %1;" : "=r"(u) : "f"(x));
    return u;
}
__device__ __forceinline__ void mma_tf32(float* c, const uint32_t* a, const uint32_t* b) {
    asm volatile(
        "mma.sync.aligned.m16n8k8.row.col.f32.tf32.tf32.f32 "
        "{%0,%1,%2,%3}, {%4,%5,%6,%7}, {%8,%9}, {%0,%1,%2,%3};"
        : "+f"(c[0]), "+f"(c[1]), "+f"(c[2]), "+f"(c[3])
        : "r"(a[0]), "r"(a[1]), "r"(a[2]), "r"(a[3]), "r"(b[0]), "r"(b[1]));
}

// ---------------- HMMA tf32 GEMM: g_z = A @ W^T + bias ----------------------
// BM=128, BN=128, BK=32; 256 threads = 8 warps; warp tile 32x64 (2x8 frags).
// SMEM stride 36 floats -> conflict-free fragment gathers (4g+q distinct).
template <int K, bool UseExt>
__global__ __launch_bounds__(256) void gemm_mma(
    const float* __restrict__ Aext, const float* __restrict__ W,
    const float* __restrict__ bias)
{
    const float* __restrict__ A = UseExt ? Aext : (const float*)g_h1;

    __shared__ uint32_t sA[128][36];   // [row][k], tf32 bits
    __shared__ uint32_t sW[128][36];   // [n][k],  tf32 bits

    int tid  = threadIdx.x;
    int wid  = tid >> 5, lane = tid & 31;
    int wr   = wid & 3;        // 4 warps along M -> 32 rows each
    int wc   = wid >> 2;       // 2 warps along N -> 64 cols each
    int g4   = lane >> 2;      // 0..7
    int q4   = lane & 3;       // 0..3
    int m0   = blockIdx.x * 128;

    float acc[2][8][4];
#pragma unroll
    for (int mt = 0; mt < 2; ++mt)
#pragma unroll
        for (int nt = 0; nt < 8; ++nt)
#pragma unroll
            for (int j = 0; j < 4; ++j) acc[mt][nt][j] = 0.f;

    for (int k0 = 0; k0 < K; k0 += 32) {
        // load A tile [128 x 32] and W tile [128 x 32], rounded to tf32
#pragma unroll
        for (int t = tid; t < 1024; t += 256) {
            int row = t >> 3, q = t & 7;
            int gr = m0 + row;
            float4 v = make_float4(0.f, 0.f, 0.f, 0.f);
            if (gr < N_NODES) v = ((const float4*)A)[gr * (K / 4) + (k0 >> 2) + q];
            sA[row][q * 4 + 0] = tf32r(v.x);
            sA[row][q * 4 + 1] = tf32r(v.y);
            sA[row][q * 4 + 2] = tf32r(v.z);
            sA[row][q * 4 + 3] = tf32r(v.w);
        }
#pragma unroll
        for (int t = tid; t < 1024; t += 256) {
            int row = t >> 3, q = t & 7;
            float4 v = ((const float4*)W)[row * (K / 4) + (k0 >> 2) + q];
            sW[row][q * 4 + 0] = tf32r(v.x);
            sW[row][q * 4 + 1] = tf32r(v.y);
            sW[row][q * 4 + 2] = tf32r(v.z);
            sW[row][q * 4 + 3] = tf32r(v.w);
        }
        __syncthreads();

#pragma unroll
        for (int kk = 0; kk < 32; kk += 8) {
            uint32_t afr[2][4];
#pragma unroll
            for (int mt = 0; mt < 2; ++mt) {
                int rb = wr * 32 + mt * 16;
                afr[mt][0] = sA[rb + g4][kk + q4];
                afr[mt][1] = sA[rb + 8 + g4][kk + q4];
                afr[mt][2] = sA[rb + g4][kk + 4 + q4];
                afr[mt][3] = sA[rb + 8 + g4][kk + 4 + q4];
            }
#pragma unroll
            for (int nt = 0; nt < 8; ++nt) {
                int cb = wc * 64 + nt * 8;
                uint32_t bfr[2];
                bfr[0] = sW[cb + g4][kk + q4];
                bfr[1] = sW[cb + g4][kk + 4 + q4];
#pragma unroll
                for (int mt = 0; mt < 2; ++mt)
                    mma_tf32(acc[mt][nt], afr[mt], bfr);
            }
        }
        __syncthreads();
    }

    // epilogue: + bias, store z
#pragma unroll
    for (int mt = 0; mt < 2; ++mt) {
        int r0 = m0 + wr * 32 + mt * 16 + g4;
        int r1 = r0 + 8;
#pragma unroll
        for (int nt = 0; nt < 8; ++nt) {
            int cb = wc * 64 + nt * 8 + q4 * 2;
            float bx = __ldg(&bias[cb]), by = __ldg(&bias[cb + 1]);
            if (r0 < N_NODES)
                *(float2*)&g_z[r0 * 128 + cb] =
                    make_float2(acc[mt][nt][0] + bx, acc[mt][nt][1] + by);
            if (r1 < N_NODES)
                *(float2*)&g_z[r1 * 128 + cb] =
                    make_float2(acc[mt][nt][2] + bx, acc[mt][nt][3] + by);
        }
    }
}

// ---------------- per-node attention scalars: s_src, s_dst ------------------
__global__ void attn_kernel(const float* __restrict__ a) {
    int gt   = blockIdx.x * blockDim.x + threadIdx.x;
    int node = gt >> 5;
    int lane = gt & 31;
    if (node >= N_NODES) return;
    float4 zv = ((const float4*)g_z)[node * 32 + lane];
    float4 as = ((const float4*)a)[lane];
    float4 ad = ((const float4*)a)[lane + 32];
    float ss = zv.x * as.x + zv.y * as.y + zv.z * as.z + zv.w * as.w;
    float sd = zv.x * ad.x + zv.y * ad.y + zv.z * ad.z + zv.w * ad.w;
#pragma unroll
    for (int o = 16; o > 0; o >>= 1) {
        ss += __shfl_down_sync(0xffffffffu, ss, o);
        sd += __shfl_down_sync(0xffffffffu, sd, o);
    }
    if (lane == 0) { g_ssrc[node] = ss; g_sdst[node] = sd; }
}

// ---------------- fused softmax + weighted aggregation + ELU ----------------
template <bool ToExt>
__global__ __launch_bounds__(256) void agg_kernel(const int* __restrict__ src,
                                                  const float* __restrict__ ab_ptr,
                                                  float* __restrict__ out_ext)
{
    float* __restrict__ out = ToExt ? out_ext : (float*)g_h1;
    int gt   = blockIdx.x * blockDim.x + threadIdx.x;
    int node = gt >> 5;
    int lane = gt & 31;
    if (node >= N_NODES) return;
    int beg = g_off[node], end = g_off[node + 1], deg = end - beg;
    float sdn = g_sdst[node] + ab_ptr[0];

    // stash first 128 edges (4 per lane); recompute tail (degree>128 is rare)
    float ev[4]; int snv[4];
    float m = NEG_INF;
#pragma unroll
    for (int l = 0; l < 4; ++l) {
        int s = beg + lane + l * 32;
        float e = NEG_INF; int sn = 0;
        if (s < end) {
            int eid = g_eid[s];
            sn = src[eid];
            e = g_ssrc[sn] + sdn;
            e = (e > 0.f) ? e : LEAKY * e;
        }
        ev[l] = e; snv[l] = sn;
        m = fmaxf(m, e);
    }
    for (int s = beg + 128 + lane; s < end; s += 32) {
        int eid = g_eid[s];
        float e = g_ssrc[src[eid]] + sdn;
        e = (e > 0.f) ? e : LEAKY * e;
        m = fmaxf(m, e);
    }
#pragma unroll
    for (int o = 16; o > 0; o >>= 1) m = fmaxf(m, __shfl_xor_sync(0xffffffffu, m, o));

    float S = 0.f;
#pragma unroll
    for (int l = 0; l < 4; ++l)
        if (beg + lane + l * 32 < end) S += __expf(ev[l] - m);
    for (int s = beg + 128 + lane; s < end; s += 32) {
        int eid = g_eid[s];
        float e = g_ssrc[src[eid]] + sdn;
        e = (e > 0.f) ? e : LEAKY * e;
        S += __expf(e - m);
    }
#pragma unroll
    for (int o = 16; o > 0; o >>= 1) S += __shfl_xor_sync(0xffffffffu, S, o);
    float inv = (deg > 0) ? (1.f / S) : 0.f;

    float4 acc = make_float4(0.f, 0.f, 0.f, 0.f);
    int nin = deg < 128 ? deg : 128;
#pragma unroll 4
    for (int i = 0; i < nin; ++i) {
        int sl = i >> 5, ln = i & 31;                 // uniform across warp
        float esel = (sl == 0) ? ev[0] : (sl == 1) ? ev[1] : (sl == 2) ? ev[2] : ev[3];
        int   ssel = (sl == 0) ? snv[0] : (sl == 1) ? snv[1] : (sl == 2) ? snv[2] : snv[3];
        float e  = __shfl_sync(0xffffffffu, esel, ln);
        int   sn = __shfl_sync(0xffffffffu, ssel, ln);
        float w  = __expf(e - m) * inv;
        float4 zv = ((const float4*)g_z)[sn * 32 + lane];
        acc.x += w * zv.x; acc.y += w * zv.y; acc.z += w * zv.z; acc.w += w * zv.w;
    }
    for (int s = beg + 128; s < end; ++s) {           // rare tail (deg > 128)
        int eid = g_eid[s];
        int sn  = src[eid];
        float e = g_ssrc[sn] + sdn;
        e = (e > 0.f) ? e : LEAKY * e;
        float w = __expf(e - m) * inv;
        float4 zv = ((const float4*)g_z)[sn * 32 + lane];
        acc.x += w * zv.x; acc.y += w * zv.y; acc.z += w * zv.z; acc.w += w * zv.w;
    }
    // ELU (alpha = 1)
    acc.x = (acc.x > 0.f) ? acc.x : (__expf(acc.x) - 1.f);
    acc.y = (acc.y > 0.f) ? acc.y : (__expf(acc.y) - 1.f);
    acc.z = (acc.z > 0.f) ? acc.z : (__expf(acc.z) - 1.f);
    acc.w = (acc.w > 0.f) ? acc.w : (__expf(acc.w) - 1.f);
    ((float4*)out)[node * 32 + lane] = acc;
}

// ---------------- launch ------------------------------------------------------
extern "C" void kernel_launch(void* const* d_in, const int* in_sizes, int n_in,
                              void* d_out, int out_size) {
    const float* h   = (const float*)d_in[0];
    const int*   src = (const int*)d_in[1];
    const int*   dst = (const int*)d_in[2];
    const float* W1  = (const float*)d_in[3];
    const float* b1  = (const float*)d_in[4];
    const float* a1  = (const float*)d_in[5];
    const float* ab1 = (const float*)d_in[6];
    const float* W2  = (const float*)d_in[7];
    const float* b2  = (const float*)d_in[8];
    const float* a2  = (const float*)d_in[9];
    const float* ab2 = (const float*)d_in[10];
    float* out = (float*)d_out;

    const int NB_N = (N_NODES + 255) / 256;
    const int NB_E = (N_EDGES + 255) / 256;
    const int NB_W = (N_NODES + 7) / 8;
    const int NB_G = (N_NODES + 127) / 128;   // 391 tiles

    // CSR by dst (topology only; shared by both layers)
    zero_cnt_kernel<<<NB_N, 256>>>();
    hist_kernel<<<NB_E, 256>>>(dst);
    scan_kernel<<<1, 1024>>>();
    fill_kernel<<<NB_E, 256>>>(dst);

    // ----- layer 1 -----
    gemm_mma<IN_DIM, true><<<NB_G, 256>>>(h, W1, b1);
    attn_kernel<<<NB_W, 256>>>(a1);
    agg_kernel<false><<<NB_W, 256>>>(src, ab1, nullptr);

    // ----- layer 2 -----
    gemm_mma<HID, false><<<NB_G, 256>>>(nullptr, W2, b2);
    attn_kernel<<<NB_W, 256>>>(a2);
    agg_kernel<true><<<NB_W, 256>>>(src, ab2, out);
}

// round 5
// speedup vs baseline: 1.3669x; 1.0747x over previous
#include <cuda_runtime.h>
#include <cuda_bf16.h>
#include <cstdint>
#include <limits.h>

#define N_NODES 50000
#define N_EDGES 800000
#define IN_DIM  256
#define HID     128
#define LEAKY   0.01f
#define NEG_INF __int_as_float(0xff800000)

// ---------------- scratch (device globals; device-side use ONLY) -------------
__device__ __align__(16) float g_z[N_NODES * HID];   // z = fc(h) (pre-activation)
__device__ __align__(16) float g_h1[N_NODES * HID];  // layer-1 output (post ELU)
__device__ float g_ssrc[N_NODES];
__device__ float g_sdst[N_NODES];
__device__ int   g_cnt[N_NODES];
__device__ int   g_off[N_NODES + 1];
__device__ int   g_cur[N_NODES];
__device__ int   g_esrc[N_EDGES];      // CSR (by dst) -> src node id (direct)

// ---------------- CSR build --------------------------------------------------
__global__ void zero_cnt_kernel() {
    int i = blockIdx.x * blockDim.x + threadIdx.x;
    if (i < N_NODES) g_cnt[i] = 0;
}
// 4 edges per thread (N_EDGES % 4 == 0)
__global__ void hist_kernel(const int* __restrict__ dst) {
    int i = blockIdx.x * blockDim.x + threadIdx.x;
    if (i * 4 < N_EDGES) {
        int4 d = ((const int4*)dst)[i];
        atomicAdd(&g_cnt[d.x], 1);
        atomicAdd(&g_cnt[d.y], 1);
        atomicAdd(&g_cnt[d.z], 1);
        atomicAdd(&g_cnt[d.w], 1);
    }
}
__global__ void scan_kernel() {
    __shared__ int sums[1024];
    int tid = threadIdx.x;
    const int chunk = (N_NODES + 1023) / 1024;
    int begin = tid * chunk;
    int end   = begin + chunk; if (end > N_NODES) end = N_NODES;
    if (begin > N_NODES) begin = N_NODES;
    int s = 0;
    for (int i = begin; i < end; ++i) s += g_cnt[i];
    sums[tid] = s;
    __syncthreads();
    for (int off = 1; off < 1024; off <<= 1) {
        int add = 0;
        if (tid >= off) add = sums[tid - off];
        __syncthreads();
        sums[tid] += add;
        __syncthreads();
    }
    int prefix = (tid == 0) ? 0 : sums[tid - 1];
    for (int i = begin; i < end; ++i) {
        g_off[i] = prefix;
        g_cur[i] = prefix;
        prefix += g_cnt[i];
    }
    if (tid == 0) g_off[N_NODES] = sums[1023];
}
// 4 edges per thread; stores src id directly (coalesced src read here,
// coalesced g_esrc read later in agg)
__global__ void fill_kernel(const int* __restrict__ dst,
                            const int* __restrict__ src) {
    int i = blockIdx.x * blockDim.x + threadIdx.x;
    if (i * 4 < N_EDGES) {
        int4 d = ((const int4*)dst)[i];
        int4 s = ((const int4*)src)[i];
        int p0 = atomicAdd(&g_cur[d.x], 1);
        int p1 = atomicAdd(&g_cur[d.y], 1);
        int p2 = atomicAdd(&g_cur[d.z], 1);
        int p3 = atomicAdd(&g_cur[d.w], 1);
        g_esrc[p0] = s.x;
        g_esrc[p1] = s.y;
        g_esrc[p2] = s.z;
        g_esrc[p3] = s.w;
    }
}

// ---------------- tf32 helpers ----------------------------------------------
__device__ __forceinline__ uint32_t tf32r(float x) {
    uint32_t u;
    asm("cvt.rn.tf32.f32 %0, %1;" : "=r"(u) : "f"(x));
    return u;
}
__device__ __forceinline__ void mma_tf32(float* c, const uint32_t* a, const uint32_t* b) {
    asm volatile(
        "mma.sync.aligned.m16n8k8.row.col.f32.tf32.tf32.f32 "
        "{%0,%1,%2,%3}, {%4,%5,%6,%7}, {%8,%9}, {%0,%1,%2,%3};"
        : "+f"(c[0]), "+f"(c[1]), "+f"(c[2]), "+f"(c[3])
        : "r"(a[0]), "r"(a[1]), "r"(a[2]), "r"(a[3]), "r"(b[0]), "r"(b[1]));
}

// ---------------- HMMA tf32 GEMM: g_z = A @ W^T + bias, fused attn dots -----
// BM=128, BN=128, BK=32; 256 threads = 8 warps; warp tile 32x64 (2x8 frags).
template <int K, bool UseExt>
__global__ __launch_bounds__(256) void gemm_mma(
    const float* __restrict__ Aext, const float* __restrict__ W,
    const float* __restrict__ bias, const float* __restrict__ avec)
{
    const float* __restrict__ A = UseExt ? Aext : (const float*)g_h1;

    __shared__ uint32_t sA[128][36];   // [row][k], tf32 bits
    __shared__ uint32_t sW[128][36];   // [n][k],  tf32 bits
    __shared__ float sSS[128];
    __shared__ float sSD[128];

    int tid  = threadIdx.x;
    int wid  = tid >> 5, lane = tid & 31;
    int wr   = wid & 3;        // 4 warps along M -> 32 rows each
    int wc   = wid >> 2;       // 2 warps along N -> 64 cols each
    int g4   = lane >> 2;      // 0..7
    int q4   = lane & 3;       // 0..3
    int m0   = blockIdx.x * 128;

    float acc[2][8][4];
#pragma unroll
    for (int mt = 0; mt < 2; ++mt)
#pragma unroll
        for (int nt = 0; nt < 8; ++nt)
#pragma unroll
            for (int j = 0; j < 4; ++j) acc[mt][nt][j] = 0.f;

    for (int k0 = 0; k0 < K; k0 += 32) {
#pragma unroll
        for (int t = tid; t < 1024; t += 256) {
            int row = t >> 3, q = t & 7;
            int gr = m0 + row;
            float4 v = make_float4(0.f, 0.f, 0.f, 0.f);
            if (gr < N_NODES) v = ((const float4*)A)[gr * (K / 4) + (k0 >> 2) + q];
            sA[row][q * 4 + 0] = tf32r(v.x);
            sA[row][q * 4 + 1] = tf32r(v.y);
            sA[row][q * 4 + 2] = tf32r(v.z);
            sA[row][q * 4 + 3] = tf32r(v.w);
        }
#pragma unroll
        for (int t = tid; t < 1024; t += 256) {
            int row = t >> 3, q = t & 7;
            float4 v = ((const float4*)W)[row * (K / 4) + (k0 >> 2) + q];
            sW[row][q * 4 + 0] = tf32r(v.x);
            sW[row][q * 4 + 1] = tf32r(v.y);
            sW[row][q * 4 + 2] = tf32r(v.z);
            sW[row][q * 4 + 3] = tf32r(v.w);
        }
        __syncthreads();

#pragma unroll
        for (int kk = 0; kk < 32; kk += 8) {
            uint32_t afr[2][4];
#pragma unroll
            for (int mt = 0; mt < 2; ++mt) {
                int rb = wr * 32 + mt * 16;
                afr[mt][0] = sA[rb + g4][kk + q4];
                afr[mt][1] = sA[rb + 8 + g4][kk + q4];
                afr[mt][2] = sA[rb + g4][kk + 4 + q4];
                afr[mt][3] = sA[rb + 8 + g4][kk + 4 + q4];
            }
#pragma unroll
            for (int nt = 0; nt < 8; ++nt) {
                int cb = wc * 64 + nt * 8;
                uint32_t bfr[2];
                bfr[0] = sW[cb + g4][kk + q4];
                bfr[1] = sW[cb + g4][kk + 4 + q4];
#pragma unroll
                for (int mt = 0; mt < 2; ++mt)
                    mma_tf32(acc[mt][nt], afr[mt], bfr);
            }
        }
        __syncthreads();
    }

    // zero the per-row reduction buffer
    if (tid < 128) { sSS[tid] = 0.f; sSD[tid] = 0.f; }
    __syncthreads();

    // epilogue: + bias, store z, accumulate attention dots per row
    float ssl[2][2] = {{0.f, 0.f}, {0.f, 0.f}};   // [mt][row-half] ss
    float sdl[2][2] = {{0.f, 0.f}, {0.f, 0.f}};
#pragma unroll
    for (int mt = 0; mt < 2; ++mt) {
        int r0 = m0 + wr * 32 + mt * 16 + g4;
        int r1 = r0 + 8;
#pragma unroll
        for (int nt = 0; nt < 8; ++nt) {
            int cb = wc * 64 + nt * 8 + q4 * 2;
            float bx = __ldg(&bias[cb]), by = __ldg(&bias[cb + 1]);
            float asx = __ldg(&avec[cb]),       asy = __ldg(&avec[cb + 1]);
            float adx = __ldg(&avec[128 + cb]), ady = __ldg(&avec[128 + cb + 1]);
            float v0 = acc[mt][nt][0] + bx, v1 = acc[mt][nt][1] + by;
            float v2 = acc[mt][nt][2] + bx, v3 = acc[mt][nt][3] + by;
            ssl[mt][0] += v0 * asx + v1 * asy;
            sdl[mt][0] += v0 * adx + v1 * ady;
            ssl[mt][1] += v2 * asx + v3 * asy;
            sdl[mt][1] += v2 * adx + v3 * ady;
            if (r0 < N_NODES) *(float2*)&g_z[r0 * 128 + cb] = make_float2(v0, v1);
            if (r1 < N_NODES) *(float2*)&g_z[r1 * 128 + cb] = make_float2(v2, v3);
        }
        int lr0 = wr * 32 + mt * 16 + g4;
        atomicAdd(&sSS[lr0], ssl[mt][0]);
        atomicAdd(&sSD[lr0], sdl[mt][0]);
        atomicAdd(&sSS[lr0 + 8], ssl[mt][1]);
        atomicAdd(&sSD[lr0 + 8], sdl[mt][1]);
    }
    __syncthreads();
    if (tid < 128 && m0 + tid < N_NODES) {
        g_ssrc[m0 + tid] = sSS[tid];
        g_sdst[m0 + tid] = sSD[tid];
    }
}

// ---------------- fused softmax + weighted aggregation + ELU ----------------
template <bool ToExt>
__global__ __launch_bounds__(256) void agg_kernel(const float* __restrict__ ab_ptr,
                                                  float* __restrict__ out_ext)
{
    float* __restrict__ out = ToExt ? out_ext : (float*)g_h1;
    int gt   = blockIdx.x * blockDim.x + threadIdx.x;
    int node = gt >> 5;
    int lane = gt & 31;
    if (node >= N_NODES) return;
    int beg = g_off[node], end = g_off[node + 1], deg = end - beg;
    float sdn = g_sdst[node] + ab_ptr[0];

    // stash first 128 edges (4 per lane, coalesced); recompute rare tail
    float ev[4]; int snv[4];
    float m = NEG_INF;
#pragma unroll
    for (int l = 0; l < 4; ++l) {
        int s = beg + lane + l * 32;
        float e = NEG_INF; int sn = 0;
        if (s < end) {
            sn = g_esrc[s];
            e = g_ssrc[sn] + sdn;
            e = (e > 0.f) ? e : LEAKY * e;
        }
        ev[l] = e; snv[l] = sn;
        m = fmaxf(m, e);
    }
    for (int s = beg + 128 + lane; s < end; s += 32) {
        float e = g_ssrc[g_esrc[s]] + sdn;
        e = (e > 0.f) ? e : LEAKY * e;
        m = fmaxf(m, e);
    }
#pragma unroll
    for (int o = 16; o > 0; o >>= 1) m = fmaxf(m, __shfl_xor_sync(0xffffffffu, m, o));

    float S = 0.f;
#pragma unroll
    for (int l = 0; l < 4; ++l)
        if (beg + lane + l * 32 < end) S += __expf(ev[l] - m);
    for (int s = beg + 128 + lane; s < end; s += 32) {
        float e = g_ssrc[g_esrc[s]] + sdn;
        e = (e > 0.f) ? e : LEAKY * e;
        S += __expf(e - m);
    }
#pragma unroll
    for (int o = 16; o > 0; o >>= 1) S += __shfl_xor_sync(0xffffffffu, S, o);
    float inv = (deg > 0) ? (1.f / S) : 0.f;

    float4 acc = make_float4(0.f, 0.f, 0.f, 0.f);
    int nin = deg < 128 ? deg : 128;
#pragma unroll 4
    for (int i = 0; i < nin; ++i) {
        int sl = i >> 5, ln = i & 31;                 // uniform across warp
        float esel = (sl == 0) ? ev[0] : (sl == 1) ? ev[1] : (sl == 2) ? ev[2] : ev[3];
        int   ssel = (sl == 0) ? snv[0] : (sl == 1) ? snv[1] : (sl == 2) ? snv[2] : snv[3];
        float e  = __shfl_sync(0xffffffffu, esel, ln);
        int   sn = __shfl_sync(0xffffffffu, ssel, ln);
        float w  = __expf(e - m) * inv;
        float4 zv = ((const float4*)g_z)[sn * 32 + lane];
        acc.x += w * zv.x; acc.y += w * zv.y; acc.z += w * zv.z; acc.w += w * zv.w;
    }
    for (int s = beg + 128; s < end; ++s) {           // rare tail (deg > 128)
        int sn  = g_esrc[s];
        float e = g_ssrc[sn] + sdn;
        e = (e > 0.f) ? e : LEAKY * e;
        float w = __expf(e - m) * inv;
        float4 zv = ((const float4*)g_z)[sn * 32 + lane];
        acc.x += w * zv.x; acc.y += w * zv.y; acc.z += w * zv.z; acc.w += w * zv.w;
    }
    // ELU (alpha = 1)
    acc.x = (acc.x > 0.f) ? acc.x : (__expf(acc.x) - 1.f);
    acc.y = (acc.y > 0.f) ? acc.y : (__expf(acc.y) - 1.f);
    acc.z = (acc.z > 0.f) ? acc.z : (__expf(acc.z) - 1.f);
    acc.w = (acc.w > 0.f) ? acc.w : (__expf(acc.w) - 1.f);
    ((float4*)out)[node * 32 + lane] = acc;
}

// ---------------- launch ------------------------------------------------------
extern "C" void kernel_launch(void* const* d_in, const int* in_sizes, int n_in,
                              void* d_out, int out_size) {
    const float* h   = (const float*)d_in[0];
    const int*   src = (const int*)d_in[1];
    const int*   dst = (const int*)d_in[2];
    const float* W1  = (const float*)d_in[3];
    const float* b1  = (const float*)d_in[4];
    const float* a1  = (const float*)d_in[5];
    const float* ab1 = (const float*)d_in[6];
    const float* W2  = (const float*)d_in[7];
    const float* b2  = (const float*)d_in[8];
    const float* a2  = (const float*)d_in[9];
    const float* ab2 = (const float*)d_in[10];
    float* out = (float*)d_out;

    const int NB_N  = (N_NODES + 255) / 256;
    const int NB_E4 = (N_EDGES / 4 + 255) / 256;
    const int NB_W  = (N_NODES + 7) / 8;
    const int NB_G  = (N_NODES + 127) / 128;   // 391 tiles

    // CSR by dst (topology only; shared by both layers)
    zero_cnt_kernel<<<NB_N, 256>>>();
    hist_kernel<<<NB_E4, 256>>>(dst);
    scan_kernel<<<1, 1024>>>();
    fill_kernel<<<NB_E4, 256>>>(dst, src);

    // ----- layer 1 -----
    gemm_mma<IN_DIM, true><<<NB_G, 256>>>(h, W1, b1, a1);
    agg_kernel<false><<<NB_W, 256>>>(ab1, nullptr);

    // ----- layer 2 -----
    gemm_mma<HID, false><<<NB_G, 256>>>(nullptr, W2, b2, a2);
    agg_kernel<true><<<NB_W, 256>>>(ab2, out);
}

// round 6
// speedup vs baseline: 1.8918x; 1.3840x over previous
#include <cuda_runtime.h>
#include <cuda_bf16.h>
#include <cstdint>
#include <limits.h>

#define N_NODES 50000
#define N_EDGES 800000
#define IN_DIM  256
#define HID     128
#define LEAKY   0.01f
#define NEG_INF __int_as_float(0xff800000)

// ---------------- scratch (device globals; device-side use ONLY) -------------
__device__ __align__(16) float    g_z[N_NODES * HID];   // z = fc(h) (pre-activation)
__device__ __align__(16) float    g_h1[N_NODES * HID];  // layer-1 out (ELU, tf32-rounded)
__device__ __align__(16) uint32_t g_W1r[HID * IN_DIM];  // tf32-rounded W1
__device__ __align__(16) uint32_t g_W2r[HID * HID];     // tf32-rounded W2
__device__ float g_ssrc[N_NODES];
__device__ float g_sdst[N_NODES];
__device__ int   g_cnt[N_NODES];
__device__ int   g_off[N_NODES + 1];
__device__ int   g_cur[N_NODES];
__device__ int   g_esrc[N_EDGES];      // CSR (by dst) -> src node id

// ---------------- small helpers ----------------------------------------------
__device__ __forceinline__ uint32_t smem_u32(const void* p) {
    uint32_t a;
    asm("{ .reg .u64 t; cvta.to.shared.u64 t, %1; cvt.u32.u64 %0, t; }" : "=r"(a) : "l"(p));
    return a;
}
__device__ __forceinline__ uint32_t tf32r(float x) {
    uint32_t u;
    asm("cvt.rn.tf32.f32 %0, %1;" : "=r"(u) : "f"(x));
    return u;
}
__device__ __forceinline__ uint32_t tf32r_u(uint32_t v) {
    uint32_t o;
    asm("cvt.rn.tf32.f32 %0, %1;" : "=r"(o) : "f"(__uint_as_float(v)));
    return o;
}
__device__ __forceinline__ void cp16z(uint32_t dst, const void* src, bool valid) {
    int sz = valid ? 16 : 0;
    asm volatile("cp.async.cg.shared.global [%0], [%1], 16, %2;"
                 :: "r"(dst), "l"(src), "r"(sz));
}
__device__ __forceinline__ void cp16(uint32_t dst, const void* src) {
    asm volatile("cp.async.cg.shared.global [%0], [%1], 16;" :: "r"(dst), "l"(src));
}
#define CP_COMMIT() asm volatile("cp.async.commit_group;" ::: "memory")
#define CP_WAIT(N)  asm volatile("cp.async.wait_group %0;" :: "n"(N) : "memory")

__device__ __forceinline__ void mma_tf32(float* c, const uint32_t* a, const uint32_t* b) {
    asm volatile(
        "mma.sync.aligned.m16n8k8.row.col.f32.tf32.tf32.f32 "
        "{%0,%1,%2,%3}, {%4,%5,%6,%7}, {%8,%9}, {%0,%1,%2,%3};"
        : "+f"(c[0]), "+f"(c[1]), "+f"(c[2]), "+f"(c[3])
        : "r"(a[0]), "r"(a[1]), "r"(a[2]), "r"(a[3]), "r"(b[0]), "r"(b[1]));
}

// ---------------- CSR build --------------------------------------------------
__global__ void zero_cnt_kernel() {
    int i = blockIdx.x * blockDim.x + threadIdx.x;
    if (i < N_NODES) g_cnt[i] = 0;
}
__global__ void hist_kernel(const int* __restrict__ dst) {
    int i = blockIdx.x * blockDim.x + threadIdx.x;
    if (i * 4 < N_EDGES) {
        int4 d = ((const int4*)dst)[i];
        atomicAdd(&g_cnt[d.x], 1);
        atomicAdd(&g_cnt[d.y], 1);
        atomicAdd(&g_cnt[d.z], 1);
        atomicAdd(&g_cnt[d.w], 1);
    }
}
__global__ void scan_kernel() {
    __shared__ int sums[1024];
    int tid = threadIdx.x;
    const int chunk = (N_NODES + 1023) / 1024;
    int begin = tid * chunk;
    int end   = begin + chunk; if (end > N_NODES) end = N_NODES;
    if (begin > N_NODES) begin = N_NODES;
    int s = 0;
    for (int i = begin; i < end; ++i) s += g_cnt[i];
    sums[tid] = s;
    __syncthreads();
    for (int off = 1; off < 1024; off <<= 1) {
        int add = 0;
        if (tid >= off) add = sums[tid - off];
        __syncthreads();
        sums[tid] += add;
        __syncthreads();
    }
    int prefix = (tid == 0) ? 0 : sums[tid - 1];
    for (int i = begin; i < end; ++i) {
        g_off[i] = prefix;
        g_cur[i] = prefix;
        prefix += g_cnt[i];
    }
    if (tid == 0) g_off[N_NODES] = sums[1023];
}
__global__ void fill_kernel(const int* __restrict__ dst,
                            const int* __restrict__ src) {
    int i = blockIdx.x * blockDim.x + threadIdx.x;
    if (i * 4 < N_EDGES) {
        int4 d = ((const int4*)dst)[i];
        int4 s = ((const int4*)src)[i];
        int p0 = atomicAdd(&g_cur[d.x], 1);
        int p1 = atomicAdd(&g_cur[d.y], 1);
        int p2 = atomicAdd(&g_cur[d.z], 1);
        int p3 = atomicAdd(&g_cur[d.w], 1);
        g_esrc[p0] = s.x;
        g_esrc[p1] = s.y;
        g_esrc[p2] = s.z;
        g_esrc[p3] = s.w;
    }
}

// ---------------- W pre-round to tf32 ----------------------------------------
__global__ void round_w_kernel(const float* __restrict__ W1,
                               const float* __restrict__ W2) {
    int i = blockIdx.x * blockDim.x + threadIdx.x;
    if (i < HID * IN_DIM) g_W1r[i] = tf32r(W1[i]);
    if (i < HID * HID)    g_W2r[i] = tf32r(W2[i]);
}

// ---------------- cp.async double-buffered tf32 GEMM -------------------------
// g_z = A @ W^T + bias; fused attention dots -> g_ssrc / g_sdst.
// BM=128, BN=128, BK=32; 256 threads = 8 warps; warp tile 32x64.
// Dynamic smem: A[2][128][36] | W[2][128][36] | sSS[128] | sSD[128]
#define GEMM_SMEM (4 * 18432 + 1024)

template <int K, bool L1>
__global__ __launch_bounds__(256) void gemm_mma(
    const float* __restrict__ Aext, const float* __restrict__ bias,
    const float* __restrict__ avec)
{
    const float*    __restrict__ A  = L1 ? Aext : (const float*)g_h1;
    const uint32_t* __restrict__ Wr = L1 ? g_W1r : g_W2r;

    extern __shared__ __align__(16) char dsm[];
    uint32_t* sAb = (uint32_t*)dsm;                    // 2 stages x 4608 words
    uint32_t* sWb = (uint32_t*)(dsm + 2 * 18432);
    float*    sSS = (float*)(dsm + 4 * 18432);
    float*    sSD = sSS + 128;
    uint32_t  smA = smem_u32(sAb), smW = smem_u32(sWb);

    int tid  = threadIdx.x;
    int wid  = tid >> 5, lane = tid & 31;
    int wr   = wid & 3;        // 4 warps along M
    int wc   = wid >> 2;       // 2 warps along N
    int g4   = lane >> 2;
    int q4   = lane & 3;
    int m0   = blockIdx.x * 128;

    // per-thread fixed load slots: 4 rows x 1 float4 each for A and W
    int lrow = tid >> 1;                   // unused placeholder (kept simple below)
    (void)lrow;

    float acc[2][8][4];
#pragma unroll
    for (int mt = 0; mt < 2; ++mt)
#pragma unroll
        for (int nt = 0; nt < 8; ++nt)
#pragma unroll
            for (int j = 0; j < 4; ++j) acc[mt][nt][j] = 0.f;

    const int NT = K / 32;

    auto load_tile = [&](int t, int stage) {
        int k0 = t * 32;
#pragma unroll
        for (int x = tid; x < 1024; x += 256) {      // 128 rows x 8 float4
            int row = x >> 3, q = x & 7;
            int gr = m0 + row;
            uint32_t dA = smA + stage * 18432 + (row * 36 + q * 4) * 4;
            cp16z(dA, &((const float4*)A)[(size_t)gr * (K / 4) + (k0 >> 2) + q],
                  gr < N_NODES);
            uint32_t dW = smW + stage * 18432 + (row * 36 + q * 4) * 4;
            cp16(dW, &((const float4*)Wr)[(size_t)row * (K / 4) + (k0 >> 2) + q]);
        }
        CP_COMMIT();
    };

    load_tile(0, 0);
    for (int t = 0; t < NT; ++t) {
        int cur = t & 1;
        if (t + 1 < NT) { load_tile(t + 1, (t + 1) & 1); CP_WAIT(1); }
        else            { CP_WAIT(0); }
        __syncthreads();

        const uint32_t* Ab = sAb + cur * 4608;
        const uint32_t* Wb = sWb + cur * 4608;
#pragma unroll
        for (int kk = 0; kk < 32; kk += 8) {
            uint32_t afr[2][4];
#pragma unroll
            for (int mt = 0; mt < 2; ++mt) {
                int rb = wr * 32 + mt * 16;
                afr[mt][0] = Ab[(rb + g4) * 36 + kk + q4];
                afr[mt][1] = Ab[(rb + 8 + g4) * 36 + kk + q4];
                afr[mt][2] = Ab[(rb + g4) * 36 + kk + 4 + q4];
                afr[mt][3] = Ab[(rb + 8 + g4) * 36 + kk + 4 + q4];
                if (L1) {
#pragma unroll
                    for (int j = 0; j < 4; ++j) afr[mt][j] = tf32r_u(afr[mt][j]);
                }
            }
#pragma unroll
            for (int nt = 0; nt < 8; ++nt) {
                int cb = wc * 64 + nt * 8;
                uint32_t bfr[2];
                bfr[0] = Wb[(cb + g4) * 36 + kk + q4];
                bfr[1] = Wb[(cb + g4) * 36 + kk + 4 + q4];
#pragma unroll
                for (int mt = 0; mt < 2; ++mt)
                    mma_tf32(acc[mt][nt], afr[mt], bfr);
            }
        }
        __syncthreads();   // protect stage from t+2's overwrite
    }

    if (tid < 128) { sSS[tid] = 0.f; sSD[tid] = 0.f; }
    __syncthreads();

    // epilogue: + bias, store z, accumulate attention dots
#pragma unroll
    for (int mt = 0; mt < 2; ++mt) {
        float ss0 = 0.f, sd0 = 0.f, ss1 = 0.f, sd1 = 0.f;
        int r0 = m0 + wr * 32 + mt * 16 + g4;
        int r1 = r0 + 8;
#pragma unroll
        for (int nt = 0; nt < 8; ++nt) {
            int cb = wc * 64 + nt * 8 + q4 * 2;
            float bx = __ldg(&bias[cb]), by = __ldg(&bias[cb + 1]);
            float asx = __ldg(&avec[cb]),       asy = __ldg(&avec[cb + 1]);
            float adx = __ldg(&avec[128 + cb]), ady = __ldg(&avec[128 + cb + 1]);
            float v0 = acc[mt][nt][0] + bx, v1 = acc[mt][nt][1] + by;
            float v2 = acc[mt][nt][2] + bx, v3 = acc[mt][nt][3] + by;
            ss0 += v0 * asx + v1 * asy;
            sd0 += v0 * adx + v1 * ady;
            ss1 += v2 * asx + v3 * asy;
            sd1 += v2 * adx + v3 * ady;
            if (r0 < N_NODES) *(float2*)&g_z[(size_t)r0 * 128 + cb] = make_float2(v0, v1);
            if (r1 < N_NODES) *(float2*)&g_z[(size_t)r1 * 128 + cb] = make_float2(v2, v3);
        }
        int lr0 = wr * 32 + mt * 16 + g4;
        atomicAdd(&sSS[lr0], ss0);
        atomicAdd(&sSD[lr0], sd0);
        atomicAdd(&sSS[lr0 + 8], ss1);
        atomicAdd(&sSD[lr0 + 8], sd1);
    }
    __syncthreads();
    if (tid < 128 && m0 + tid < N_NODES) {
        g_ssrc[m0 + tid] = sSS[tid];
        g_sdst[m0 + tid] = sSD[tid];
    }
}

// ---------------- fused softmax + weighted aggregation + ELU ----------------
// ToExt=false: writes g_h1 (tf32-rounded so GEMM2 can skip fragment rounding)
template <bool ToExt>
__global__ __launch_bounds__(256) void agg_kernel(const float* __restrict__ ab_ptr,
                                                  float* __restrict__ out_ext)
{
    __shared__ float sWgt[8][128];
    __shared__ int   sSrc[8][128];
    float* __restrict__ out = ToExt ? out_ext : (float*)g_h1;
    int gt    = blockIdx.x * blockDim.x + threadIdx.x;
    int node  = gt >> 5;
    int lane  = gt & 31;
    int wslot = (threadIdx.x >> 5);
    if (node >= N_NODES) return;
    int beg = g_off[node], end = g_off[node + 1], deg = end - beg;
    float sdn = g_sdst[node] + ab_ptr[0];

    float ev[4]; int snv[4];
    float m = NEG_INF;
#pragma unroll
    for (int l = 0; l < 4; ++l) {
        int s = beg + lane + l * 32;
        float e = NEG_INF; int sn = 0;
        if (s < end) {
            sn = g_esrc[s];
            e = g_ssrc[sn] + sdn;
            e = (e > 0.f) ? e : LEAKY * e;
        }
        ev[l] = e; snv[l] = sn;
        m = fmaxf(m, e);
    }
    for (int s = beg + 128 + lane; s < end; s += 32) {
        float e = g_ssrc[g_esrc[s]] + sdn;
        e = (e > 0.f) ? e : LEAKY * e;
        m = fmaxf(m, e);
    }
#pragma unroll
    for (int o = 16; o > 0; o >>= 1) m = fmaxf(m, __shfl_xor_sync(0xffffffffu, m, o));

    float S = 0.f;
#pragma unroll
    for (int l = 0; l < 4; ++l)
        if (beg + lane + l * 32 < end) S += __expf(ev[l] - m);
    for (int s = beg + 128 + lane; s < end; s += 32) {
        float e = g_ssrc[g_esrc[s]] + sdn;
        e = (e > 0.f) ? e : LEAKY * e;
        S += __expf(e - m);
    }
#pragma unroll
    for (int o = 16; o > 0; o >>= 1) S += __shfl_xor_sync(0xffffffffu, S, o);
    float inv = (deg > 0) ? (1.f / S) : 0.f;

    // stash normalized weights + src ids to SMEM (broadcast-read below)
#pragma unroll
    for (int l = 0; l < 4; ++l) {
        int idx = lane + l * 32;
        if (beg + idx < end) {
            sWgt[wslot][idx] = __expf(ev[l] - m) * inv;
            sSrc[wslot][idx] = snv[l];
        }
    }
    __syncwarp();

    float4 acc = make_float4(0.f, 0.f, 0.f, 0.f);
    int nin = deg < 128 ? deg : 128;
#pragma unroll 4
    for (int i = 0; i < nin; ++i) {
        float w  = sWgt[wslot][i];
        int   sn = sSrc[wslot][i];
        float4 zv = ((const float4*)g_z)[(size_t)sn * 32 + lane];
        acc.x += w * zv.x; acc.y += w * zv.y; acc.z += w * zv.z; acc.w += w * zv.w;
    }
    for (int s = beg + 128; s < end; ++s) {           // rare tail (deg > 128)
        int sn  = g_esrc[s];
        float e = g_ssrc[sn] + sdn;
        e = (e > 0.f) ? e : LEAKY * e;
        float w = __expf(e - m) * inv;
        float4 zv = ((const float4*)g_z)[(size_t)sn * 32 + lane];
        acc.x += w * zv.x; acc.y += w * zv.y; acc.z += w * zv.z; acc.w += w * zv.w;
    }
    // ELU (alpha = 1)
    acc.x = (acc.x > 0.f) ? acc.x : (__expf(acc.x) - 1.f);
    acc.y = (acc.y > 0.f) ? acc.y : (__expf(acc.y) - 1.f);
    acc.z = (acc.z > 0.f) ? acc.z : (__expf(acc.z) - 1.f);
    acc.w = (acc.w > 0.f) ? acc.w : (__expf(acc.w) - 1.f);
    if (!ToExt) {   // pre-round for GEMM2's tf32 consumption
        acc.x = __uint_as_float(tf32r(acc.x));
        acc.y = __uint_as_float(tf32r(acc.y));
        acc.z = __uint_as_float(tf32r(acc.z));
        acc.w = __uint_as_float(tf32r(acc.w));
    }
    ((float4*)out)[(size_t)node * 32 + lane] = acc;
}

// ---------------- launch ------------------------------------------------------
extern "C" void kernel_launch(void* const* d_in, const int* in_sizes, int n_in,
                              void* d_out, int out_size) {
    const float* h   = (const float*)d_in[0];
    const int*   src = (const int*)d_in[1];
    const int*   dst = (const int*)d_in[2];
    const float* W1  = (const float*)d_in[3];
    const float* b1  = (const float*)d_in[4];
    const float* a1  = (const float*)d_in[5];
    const float* ab1 = (const float*)d_in[6];
    const float* W2  = (const float*)d_in[7];
    const float* b2  = (const float*)d_in[8];
    const float* a2  = (const float*)d_in[9];
    const float* ab2 = (const float*)d_in[10];
    float* out = (float*)d_out;

    const int NB_N  = (N_NODES + 255) / 256;
    const int NB_E4 = (N_EDGES / 4 + 255) / 256;
    const int NB_W  = (N_NODES + 7) / 8;
    const int NB_G  = (N_NODES + 127) / 128;   // 391 tiles

    cudaFuncSetAttribute(gemm_mma<IN_DIM, true>,
                         cudaFuncAttributeMaxDynamicSharedMemorySize, GEMM_SMEM);
    cudaFuncSetAttribute(gemm_mma<HID, false>,
                         cudaFuncAttributeMaxDynamicSharedMemorySize, GEMM_SMEM);

    // fork: CSR chain on s2 concurrent with W-round + GEMM1 on main stream
    cudaStream_t s2 = 0;
    cudaEvent_t evFork = nullptr, evCsr = nullptr;
    bool forked =
        cudaStreamCreateWithFlags(&s2, cudaStreamNonBlocking) == cudaSuccess &&
        cudaEventCreateWithFlags(&evFork, cudaEventDisableTiming) == cudaSuccess &&
        cudaEventCreateWithFlags(&evCsr, cudaEventDisableTiming) == cudaSuccess;
    cudaStream_t cs = forked ? s2 : (cudaStream_t)0;
    if (forked) {
        cudaEventRecord(evFork, 0);
        cudaStreamWaitEvent(s2, evFork, 0);
    }

    zero_cnt_kernel<<<NB_N, 256, 0, cs>>>();
    hist_kernel<<<NB_E4, 256, 0, cs>>>(dst);
    scan_kernel<<<1, 1024, 0, cs>>>();
    fill_kernel<<<NB_E4, 256, 0, cs>>>(dst, src);
    if (forked) cudaEventRecord(evCsr, s2);

    round_w_kernel<<<(HID * IN_DIM + 255) / 256, 256>>>(W1, W2);
    gemm_mma<IN_DIM, true><<<NB_G, 256, GEMM_SMEM>>>(h, b1, a1);

    if (forked) cudaStreamWaitEvent(0, evCsr, 0);
    agg_kernel<false><<<NB_W, 256>>>(ab1, nullptr);

    gemm_mma<HID, false><<<NB_G, 256, GEMM_SMEM>>>(nullptr, b2, a2);
    agg_kernel<true><<<NB_W, 256>>>(ab2, out);
    // streams/events intentionally not destroyed: kernel_launch executes only
    // for correctness + capture; replays run the captured graph.
}